// round 8
// baseline (speedup 1.0000x reference)
#include <cuda_runtime.h>
#include <cuda_fp16.h>
#include <cstdint>

#define B_  8
#define C_  64
#define HW_ 4096

// ---------------- scratch globals (no allocation) ----------------
__device__ __half g_q[(size_t)B_*HW_*C_];   // [b][n][c]  (scaled by log2e/8)
__device__ __half g_k[(size_t)B_*HW_*C_];   // [b][n][c]
__device__ __half g_v[(size_t)B_*HW_*C_];   // [b][n][c]

__device__ __forceinline__ uint32_t smem_u32(const void* p) {
    uint32_t a;
    asm("{ .reg .u64 t; cvta.to.shared.u64 t, %1; cvt.u32.u64 %0, t; }" : "=r"(a) : "l"(p));
    return a;
}

#define MMA16816(c, a, b0, b1)                                                  \
    asm volatile("mma.sync.aligned.m16n8k16.row.col.f32.f16.f16.f32 "           \
        "{%0,%1,%2,%3}, {%4,%5,%6,%7}, {%8,%9}, {%0,%1,%2,%3};"                 \
        : "+f"((c)[0]), "+f"((c)[1]), "+f"((c)[2]), "+f"((c)[3])                \
        : "r"((a)[0]), "r"((a)[1]), "r"((a)[2]), "r"((a)[3]), "r"(b0), "r"(b1))

#define LDSM4(r, a)                                                             \
    asm volatile("ldmatrix.sync.aligned.m8n8.x4.shared.b16 {%0,%1,%2,%3}, [%4];"\
        : "=r"((r)[0]), "=r"((r)[1]), "=r"((r)[2]), "=r"((r)[3]) : "r"(a))

#define LDSM4T(r, a)                                                            \
    asm volatile("ldmatrix.sync.aligned.m8n8.x4.trans.shared.b16 {%0,%1,%2,%3}, [%4];"\
        : "=r"((r)[0]), "=r"((r)[1]), "=r"((r)[2]), "=r"((r)[3]) : "r"(a))

#define LDSM2T(r, a)                                                            \
    asm volatile("ldmatrix.sync.aligned.m8n8.x2.trans.shared.b16 {%0,%1}, [%2];"\
        : "=r"((r)[0]), "=r"((r)[1]) : "r"(a))

// packed half2 exp2 (MUFU, one op per two values) — renamed to avoid
// colliding with cuda_fp16.h's h2exp2
__device__ __forceinline__ uint32_t pexp2_h2(__half2 x) {
    uint32_t y, xi = *reinterpret_cast<uint32_t*>(&x);
    asm("ex2.approx.f16x2 %0, %1;" : "=r"(y) : "r"(xi));
    return y;
}

#define SHIFT 5.0f   // ~E[row max] in log2 units; cancels in normalization

// ---------------------------------------------------------------------------
// QKV projection, all three matrices in one pass over the x tile.
// Outputs [b][n][c] fp16; Q pre-scaled by log2(e)/sqrt(C).
// ---------------------------------------------------------------------------
#define QKV_SMEM (64*68*4 + 3*64*65*4 + 3*64*4)

__global__ __launch_bounds__(256) void qkv_kernel(
    const float* __restrict__ x,
    const float* __restrict__ wq, const float* __restrict__ bq,
    const float* __restrict__ wk, const float* __restrict__ bk,
    const float* __restrict__ wv, const float* __restrict__ bv)
{
    extern __shared__ float smf[];
    float* xs  = smf;                 // [64][68]
    float* ws  = smf + 64*68;         // 3 x [64][65]  ws[m][c][d] = w[d][c]
    float* bsh = ws + 3*64*65;        // 3 x 64

    int tid = threadIdx.x;
    int b   = blockIdx.x >> 6;
    int n0  = (blockIdx.x & 63) << 6;
    const float* xb = x + (size_t)b*C_*HW_;

    #pragma unroll
    for (int k = 0; k < 16; k++) {
        int e = tid + 256*k; int c = e >> 6, i = e & 63;
        xs[c*68 + i] = xb[(size_t)c*HW_ + n0 + i];
    }
    #pragma unroll
    for (int k = 0; k < 16; k++) {
        int e = tid + 256*k;
        int c = e & 63, d = e >> 6;
        ws[c*65 + d]          = wq[e];
        ws[4160 + c*65 + d]   = wk[e];
        ws[8320 + c*65 + d]   = wv[e];
    }
    if (tid < 192) {
        bsh[tid] = (tid < 64) ? bq[tid] : (tid < 128) ? bk[tid - 64] : bv[tid - 128];
    }
    __syncthreads();

    int d = tid & 63, ib = (tid >> 6) << 4;
    float acc[3][16];
    #pragma unroll
    for (int k = 0; k < 16; k++) {
        acc[0][k] = bsh[d]; acc[1][k] = bsh[64 + d]; acc[2][k] = bsh[128 + d];
    }

    #pragma unroll 8
    for (int c = 0; c < 64; c++) {
        const float4* xr = (const float4*)(xs + c*68 + ib);
        float4 x0 = xr[0], x1 = xr[1], x2 = xr[2], x3 = xr[3];
        float xv[16] = {x0.x,x0.y,x0.z,x0.w, x1.x,x1.y,x1.z,x1.w,
                        x2.x,x2.y,x2.z,x2.w, x3.x,x3.y,x3.z,x3.w};
        float w0 = ws[c*65 + d], w1 = ws[4160 + c*65 + d], w2 = ws[8320 + c*65 + d];
        #pragma unroll
        for (int k = 0; k < 16; k++) {
            acc[0][k] = fmaf(xv[k], w0, acc[0][k]);
            acc[1][k] = fmaf(xv[k], w1, acc[1][k]);
            acc[2][k] = fmaf(xv[k], w2, acc[2][k]);
        }
    }

    const float scq = 0.18033688011112043f;   // log2(e)/8
    __half* qo = g_q + (size_t)b*HW_*C_;
    __half* ko = g_k + (size_t)b*HW_*C_;
    __half* vo = g_v + (size_t)b*HW_*C_;
    #pragma unroll
    for (int k = 0; k < 16; k++) {
        size_t o = (size_t)(n0 + ib + k)*C_ + d;
        qo[o] = __float2half_rn(acc[0][k]*scq);
        ko[o] = __float2half_rn(acc[1][k]);
        vo[o] = __float2half_rn(acc[2][k]);
    }
}

// ---------------------------------------------------------------------------
// Fused flash attention (HMMA, double-buffered K/V, f16x2 MUFU softmax,
// l via ones-column MMA) + mix (1x1 conv + ReLU) + 2x2 avg pool epilogue.
// One CTA per (b, 128-query tile) == one output image row.
// ---------------------------------------------------------------------------
#define PITCH 144                  // bytes per 64-half row (8 halves padding)
#define KVBUF 18432                // one K|V buffer: K 9216 + V 9216
#define SM_WMT 36864               // wmT region (16 KB)
#define ATTN_SMEM (36864 + 16384)

__global__ __launch_bounds__(256, 2) void attn_kernel(
    const float* __restrict__ wm, const float* __restrict__ bm,
    float* __restrict__ out)
{
    extern __shared__ __align__(16) char smem[];
    const uint32_t sb = smem_u32(smem);
    float* wmT = (float*)(smem + SM_WMT);   // wmT[c][d]

    int tid = threadIdx.x, wid = tid >> 5, lane = tid & 31;
    int b  = blockIdx.x >> 5;
    int it = blockIdx.x & 31;          // output row index
    int n0 = it << 7;

    const __half* kg = g_k + (size_t)b*HW_*C_;
    const __half* vg = g_v + (size_t)b*HW_*C_;

    // wmT load (once; disjoint region)
    #pragma unroll
    for (int k = 0; k < 16; k++) {
        int e = tid + 256*k;
        wmT[(e & 63)*64 + (e >> 6)] = wm[e];
    }

    const int e0 = tid, e1 = tid + 256;
    const int so0 = (e0 >> 3)*PITCH + (e0 & 7)*16;
    const int so1 = (e1 >> 3)*PITCH + (e1 & 7)*16;

    // ---- stage Q in buffer 0 region (cols 0-63 only) ----
    {
        const float4* q4 = (const float4*)(g_q + ((size_t)b*HW_ + n0)*C_);
        #pragma unroll
        for (int k = 0; k < 4; k++) {
            int e = tid + 256*k;
            *(float4*)(smem + (e >> 3)*PITCH + (e & 7)*16) = q4[e];
        }
    }
    // ones in V-region padding cols 64-71 of both buffers (never overwritten)
    if (tid < 128) {
        int row = tid & 63, buf = tid >> 6;
        uint4 ones = make_uint4(0x3C003C00u, 0x3C003C00u, 0x3C003C00u, 0x3C003C00u);
        *(uint4*)(smem + buf*KVBUF + 9216 + row*PITCH + 128) = ones;
    }
    __syncthreads();

    uint32_t qf[4][4];
    {
        int r  = 16*wid + (lane & 15);
        int cg = (lane >> 4) & 1;
        #pragma unroll
        for (int kt = 0; kt < 4; kt++)
            LDSM4(qf[kt], sb + r*PITCH + (kt*16 + cg*8)*2);
    }

    // ---- prologue: tile 0 -> regs, sync, store, tile 1 -> regs ----
    float4 rk0, rk1, rv0, rv1;
    {
        const float4* k4 = (const float4*)kg;
        const float4* v4 = (const float4*)vg;
        rk0 = k4[e0]; rk1 = k4[e1]; rv0 = v4[e0]; rv1 = v4[e1];
    }
    __syncthreads();
    *(float4*)(smem + so0) = rk0;        *(float4*)(smem + so1) = rk1;
    *(float4*)(smem + 9216 + so0) = rv0; *(float4*)(smem + 9216 + so1) = rv1;
    {
        const float4* k4 = (const float4*)(kg + (size_t)64*C_);
        const float4* v4 = (const float4*)(vg + (size_t)64*C_);
        rk0 = k4[e0]; rk1 = k4[e1]; rv0 = v4[e0]; rv1 = v4[e1];
    }

    float oacc[8][4], lacc[4];
    #pragma unroll
    for (int j = 0; j < 8; j++)
        #pragma unroll
        for (int c = 0; c < 4; c++) oacc[j][c] = 0.f;
    lacc[0] = lacc[1] = lacc[2] = lacc[3] = 0.f;

    const uint32_t klane = ((lane & 7) + ((lane >> 4) & 1)*8)*PITCH + ((lane >> 3) & 1)*16;
    const uint32_t vlane = 9216 + ((lane & 7) + ((lane >> 3) & 1)*8)*PITCH + ((lane >> 4) & 1)*16;
    const uint32_t llane = 9216 + (lane & 15)*PITCH + 128;   // ones column

    for (int t = 0; t < 64; t++) {
        __syncthreads();
        uint32_t cur = sb + (t & 1)*KVBUF;

        if (t < 63) {
            char* nb = smem + ((t + 1) & 1)*KVBUF;
            *(float4*)(nb + so0) = rk0;        *(float4*)(nb + so1) = rk1;
            *(float4*)(nb + 9216 + so0) = rv0; *(float4*)(nb + 9216 + so1) = rv1;
            if (t < 62) {
                const float4* k4 = (const float4*)(kg + (size_t)(t + 2)*64*C_);
                const float4* v4 = (const float4*)(vg + (size_t)(t + 2)*64*C_);
                rk0 = k4[e0]; rk1 = k4[e1]; rv0 = v4[e0]; rv1 = v4[e1];
            }
        }

        // ---- S = Q K^T ----
        float sacc[8][4];
        #pragma unroll
        for (int j = 0; j < 8; j++)
            #pragma unroll
            for (int c = 0; c < 4; c++) sacc[j][c] = 0.f;

        const uint32_t kb = cur + klane;
        #pragma unroll
        for (int ks = 0; ks < 4; ks++) {
            uint32_t kf0[4], kf1[4], kf2[4], kf3[4];
            LDSM4(kf0, kb + 0*(16*PITCH) + ks*32);
            LDSM4(kf1, kb + 1*(16*PITCH) + ks*32);
            LDSM4(kf2, kb + 2*(16*PITCH) + ks*32);
            LDSM4(kf3, kb + 3*(16*PITCH) + ks*32);
            MMA16816(sacc[0], qf[ks], kf0[0], kf0[1]);
            MMA16816(sacc[1], qf[ks], kf0[2], kf0[3]);
            MMA16816(sacc[2], qf[ks], kf1[0], kf1[1]);
            MMA16816(sacc[3], qf[ks], kf1[2], kf1[3]);
            MMA16816(sacc[4], qf[ks], kf2[0], kf2[1]);
            MMA16816(sacc[5], qf[ks], kf2[2], kf2[3]);
            MMA16816(sacc[6], qf[ks], kf3[0], kf3[1]);
            MMA16816(sacc[7], qf[ks], kf3[2], kf3[3]);
        }

        // ---- per 16-key chunk: shifted f16x2 exp2, l-MMA, O-MMAs ----
        const uint32_t vb = cur + vlane;
        const uint32_t lb = cur + llane;
        #pragma unroll
        for (int ks = 0; ks < 4; ks++) {
            float* s0 = sacc[2*ks];
            float* s1 = sacc[2*ks + 1];
            uint32_t ph[4];
            ph[0] = pexp2_h2(__floats2half2_rn(s0[0]-SHIFT, s0[1]-SHIFT));
            ph[1] = pexp2_h2(__floats2half2_rn(s0[2]-SHIFT, s0[3]-SHIFT));
            ph[2] = pexp2_h2(__floats2half2_rn(s1[0]-SHIFT, s1[1]-SHIFT));
            ph[3] = pexp2_h2(__floats2half2_rn(s1[2]-SHIFT, s1[3]-SHIFT));

            uint32_t lf[2];
            LDSM2T(lf, lb + ks*(16*PITCH));
            MMA16816(lacc, ph, lf[0], lf[1]);

            #pragma unroll
            for (int cg = 0; cg < 4; cg++) {
                uint32_t vf[4];
                LDSM4T(vf, vb + ks*(16*PITCH) + cg*32);
                MMA16816(oacc[2*cg],   ph, vf[0], vf[1]);
                MMA16816(oacc[2*cg+1], ph, vf[2], vf[3]);
            }
        }
    }

    // ---- epilogue: normalize, mix GEMM + ReLU, 2x2 pool, store ----
    float inv0 = 1.f / lacc[0];
    float inv1 = 1.f / lacc[2];

    __syncthreads();   // all KV-buffer reads done; reuse smem
    float* sm_o = (float*)smem;     // o^T [64 c][132]
    {
        int r  = 16*wid + (lane >> 2);
        int c0 = 2*(lane & 3);
        #pragma unroll
        for (int j = 0; j < 8; j++) {
            sm_o[(8*j + c0    )*132 + r]     = oacc[j][0]*inv0;
            sm_o[(8*j + c0 + 1)*132 + r]     = oacc[j][1]*inv0;
            sm_o[(8*j + c0    )*132 + r + 8] = oacc[j][2]*inv1;
            sm_o[(8*j + c0 + 1)*132 + r + 8] = oacc[j][3]*inv1;
        }
    }
    __syncthreads();

    // mix GEMM: mixed[t][d] = relu(bm[d] + sum_c o[t][c]*wm[d][c])
    int tx = tid & 15, ty = tid >> 4;
    float4 bmv = ((const float4*)bm)[tx];
    float acc[8][4];
    #pragma unroll
    for (int ii = 0; ii < 8; ii++) {
        acc[ii][0] = bmv.x; acc[ii][1] = bmv.y; acc[ii][2] = bmv.z; acc[ii][3] = bmv.w;
    }
    #pragma unroll 8
    for (int c = 0; c < 64; c++) {
        float4 wv = *(const float4*)(wmT + c*64 + 4*tx);
        float4 o0 = *(const float4*)(sm_o + c*132 + 8*ty);
        float4 o1 = *(const float4*)(sm_o + c*132 + 8*ty + 4);
        float ov[8] = {o0.x,o0.y,o0.z,o0.w,o1.x,o1.y,o1.z,o1.w};
        #pragma unroll
        for (int ii = 0; ii < 8; ii++) {
            acc[ii][0] = fmaf(ov[ii], wv.x, acc[ii][0]);
            acc[ii][1] = fmaf(ov[ii], wv.y, acc[ii][1]);
            acc[ii][2] = fmaf(ov[ii], wv.z, acc[ii][2]);
            acc[ii][3] = fmaf(ov[ii], wv.w, acc[ii][3]);
        }
    }
    __syncthreads();   // done reading sm_o

    float* sm_mx = (float*)smem;    // mixed [128 t][68]
    #pragma unroll
    for (int ii = 0; ii < 8; ii++) {
        float4 mv = make_float4(fmaxf(acc[ii][0], 0.f), fmaxf(acc[ii][1], 0.f),
                                fmaxf(acc[ii][2], 0.f), fmaxf(acc[ii][3], 0.f));
        *(float4*)(sm_mx + (8*ty + ii)*68 + 4*tx) = mv;
    }
    __syncthreads();

    float* ob = out + (size_t)b*C_*1024 + (size_t)it*32;
    #pragma unroll
    for (int k = 0; k < 8; k++) {
        int e = tid + 256*k;
        int j = e & 31, d = e >> 5;
        float v = sm_mx[(2*j)*68 + d] + sm_mx[(2*j + 1)*68 + d]
                + sm_mx[(64 + 2*j)*68 + d] + sm_mx[(64 + 2*j + 1)*68 + d];
        ob[(size_t)d*1024 + j] = 0.25f * v;
    }
}

extern "C" void kernel_launch(void* const* d_in, const int* in_sizes, int n_in,
                              void* d_out, int out_size)
{
    const float* x  = (const float*)d_in[0];
    const float* wq = (const float*)d_in[1];
    const float* bq = (const float*)d_in[2];
    const float* wk = (const float*)d_in[3];
    const float* bk = (const float*)d_in[4];
    const float* wv = (const float*)d_in[5];
    const float* bv = (const float*)d_in[6];
    const float* wm = (const float*)d_in[7];
    const float* bm = (const float*)d_in[8];
    float* out = (float*)d_out;

    cudaFuncSetAttribute(qkv_kernel,  cudaFuncAttributeMaxDynamicSharedMemorySize, QKV_SMEM);
    cudaFuncSetAttribute(attn_kernel, cudaFuncAttributeMaxDynamicSharedMemorySize, ATTN_SMEM);

    qkv_kernel<<<512, 256, QKV_SMEM>>>(x, wq, bq, wk, bk, wv, bv);
    attn_kernel<<<256, 256, ATTN_SMEM>>>(wm, bm, out);
}

// round 9
// speedup vs baseline: 1.5752x; 1.5752x over previous
#include <cuda_runtime.h>
#include <cuda_fp16.h>
#include <cstdint>

#define B_  8
#define C_  64
#define HW_ 4096

// ---------------- scratch globals (no allocation) ----------------
__device__ __half g_q[(size_t)B_*HW_*C_];   // [b][n][c]  (scaled by log2e/8)
__device__ __half g_k[(size_t)B_*HW_*C_];   // [b][n][c]
__device__ __half g_v[(size_t)B_*HW_*C_];   // [b][n][c]

__device__ __forceinline__ uint32_t smem_u32(const void* p) {
    uint32_t a;
    asm("{ .reg .u64 t; cvta.to.shared.u64 t, %1; cvt.u32.u64 %0, t; }" : "=r"(a) : "l"(p));
    return a;
}

#define MMA16816(c, a, b0, b1)                                                  \
    asm volatile("mma.sync.aligned.m16n8k16.row.col.f32.f16.f16.f32 "           \
        "{%0,%1,%2,%3}, {%4,%5,%6,%7}, {%8,%9}, {%0,%1,%2,%3};"                 \
        : "+f"((c)[0]), "+f"((c)[1]), "+f"((c)[2]), "+f"((c)[3])                \
        : "r"((a)[0]), "r"((a)[1]), "r"((a)[2]), "r"((a)[3]), "r"(b0), "r"(b1))

#define LDSM4(r, a)                                                             \
    asm volatile("ldmatrix.sync.aligned.m8n8.x4.shared.b16 {%0,%1,%2,%3}, [%4];"\
        : "=r"((r)[0]), "=r"((r)[1]), "=r"((r)[2]), "=r"((r)[3]) : "r"(a))

#define LDSM4T(r, a)                                                            \
    asm volatile("ldmatrix.sync.aligned.m8n8.x4.trans.shared.b16 {%0,%1,%2,%3}, [%4];"\
        : "=r"((r)[0]), "=r"((r)[1]), "=r"((r)[2]), "=r"((r)[3]) : "r"(a))

#define CP16(dst, src) asm volatile("cp.async.cg.shared.global [%0], [%1], 16;" :: "r"(dst), "l"(src))
#define CP_COMMIT()    asm volatile("cp.async.commit_group;" ::: "memory")
#define CP_WAIT1()     asm volatile("cp.async.wait_group 1;" ::: "memory")
#define CP_WAIT0()     asm volatile("cp.async.wait_group 0;" ::: "memory")

// hardware exp2 (MUFU.EX2 f32, rel err ~1e-6)
__device__ __forceinline__ float fexp2(float x) {
    float y;
    asm("ex2.approx.f32 %0, %1;" : "=f"(y) : "f"(x));
    return y;
}

// ---------------------------------------------------------------------------
// QKV projection, all three matrices in one pass over the x tile.
// Outputs [b][n][c] fp16; Q pre-scaled by log2(e)/sqrt(C).
// ---------------------------------------------------------------------------
#define QKV_SMEM (64*68*4 + 3*64*65*4 + 3*64*4)

__global__ __launch_bounds__(256) void qkv_kernel(
    const float* __restrict__ x,
    const float* __restrict__ wq, const float* __restrict__ bq,
    const float* __restrict__ wk, const float* __restrict__ bk,
    const float* __restrict__ wv, const float* __restrict__ bv)
{
    extern __shared__ float smf[];
    float* xs  = smf;                 // [64][68]
    float* ws  = smf + 64*68;         // 3 x [64][65]
    float* bsh = ws + 3*64*65;        // 3 x 64

    int tid = threadIdx.x;
    int b   = blockIdx.x >> 6;
    int n0  = (blockIdx.x & 63) << 6;
    const float* xb = x + (size_t)b*C_*HW_;

    #pragma unroll
    for (int k = 0; k < 16; k++) {
        int e = tid + 256*k; int c = e >> 6, i = e & 63;
        xs[c*68 + i] = xb[(size_t)c*HW_ + n0 + i];
    }
    #pragma unroll
    for (int k = 0; k < 16; k++) {
        int e = tid + 256*k;
        int c = e & 63, d = e >> 6;
        ws[c*65 + d]          = wq[e];
        ws[4160 + c*65 + d]   = wk[e];
        ws[8320 + c*65 + d]   = wv[e];
    }
    if (tid < 192) {
        bsh[tid] = (tid < 64) ? bq[tid] : (tid < 128) ? bk[tid - 64] : bv[tid - 128];
    }
    __syncthreads();

    int d = tid & 63, ib = (tid >> 6) << 4;
    float acc[3][16];
    #pragma unroll
    for (int k = 0; k < 16; k++) {
        acc[0][k] = bsh[d]; acc[1][k] = bsh[64 + d]; acc[2][k] = bsh[128 + d];
    }

    #pragma unroll 8
    for (int c = 0; c < 64; c++) {
        const float4* xr = (const float4*)(xs + c*68 + ib);
        float4 x0 = xr[0], x1 = xr[1], x2 = xr[2], x3 = xr[3];
        float xv[16] = {x0.x,x0.y,x0.z,x0.w, x1.x,x1.y,x1.z,x1.w,
                        x2.x,x2.y,x2.z,x2.w, x3.x,x3.y,x3.z,x3.w};
        float w0 = ws[c*65 + d], w1 = ws[4160 + c*65 + d], w2 = ws[8320 + c*65 + d];
        #pragma unroll
        for (int k = 0; k < 16; k++) {
            acc[0][k] = fmaf(xv[k], w0, acc[0][k]);
            acc[1][k] = fmaf(xv[k], w1, acc[1][k]);
            acc[2][k] = fmaf(xv[k], w2, acc[2][k]);
        }
    }

    const float scq = 0.18033688011112043f;   // log2(e)/8
    __half* qo = g_q + (size_t)b*HW_*C_;
    __half* ko = g_k + (size_t)b*HW_*C_;
    __half* vo = g_v + (size_t)b*HW_*C_;
    #pragma unroll
    for (int k = 0; k < 16; k++) {
        size_t o = (size_t)(n0 + ib + k)*C_ + d;
        qo[o] = __float2half_rn(acc[0][k]*scq);
        ko[o] = __float2half_rn(acc[1][k]);
        vo[o] = __float2half_rn(acc[2][k]);
    }
}

// ---------------------------------------------------------------------------
// Fused flash attention: HMMA + cp.async 3-stage K/V ring (one barrier/tile,
// loads fully async) + f32 MUFU softmax + mix/ReLU/2x2-pool epilogue.
// One CTA per (b, 128-query tile) == one output image row.
// ---------------------------------------------------------------------------
#define PITCH 144                  // bytes per 64-half row (8 halves padding)
#define KVBUF 18432                // one 64-key buffer: K 9216 + V 9216
#define SM_WMT (3*KVBUF)           // wmT at 55296 (16 KB)
#define ATTN_SMEM (3*KVBUF + 16384)

// async-load one 64-key K/V tile into ring buffer `buf`
__device__ __forceinline__ void load_tile_async(
    uint32_t sb, int buf, const __half* kg, const __half* vg, int kn0, int tid)
{
    uint32_t dbase = sb + buf*KVBUF;
    const char* ksrc = (const char*)(kg + (size_t)kn0*C_);
    const char* vsrc = (const char*)(vg + (size_t)kn0*C_);
    #pragma unroll
    for (int k = 0; k < 2; k++) {
        int e = tid + 256*k;                    // 512 16B-chunks per matrix
        uint32_t doff = (e >> 3)*PITCH + (e & 7)*16;
        CP16(dbase + doff,        ksrc + e*16);
        CP16(dbase + 9216 + doff, vsrc + e*16);
    }
}

__global__ __launch_bounds__(256, 2) void attn_kernel(
    const float* __restrict__ wm, const float* __restrict__ bm,
    float* __restrict__ out)
{
    extern __shared__ __align__(16) char smem[];
    const uint32_t sb = smem_u32(smem);
    float* wmT = (float*)(smem + SM_WMT);   // wmT[c][d]

    int tid = threadIdx.x, wid = tid >> 5, lane = tid & 31;
    int b  = blockIdx.x >> 5;
    int it = blockIdx.x & 31;          // output row index
    int n0 = it << 7;

    const __half* kg = g_k + (size_t)b*HW_*C_;
    const __half* vg = g_v + (size_t)b*HW_*C_;

    // ---- stage Q in buf0 region, load A fragments ----
    {
        const float4* q4 = (const float4*)(g_q + ((size_t)b*HW_ + n0)*C_);
        #pragma unroll
        for (int k = 0; k < 4; k++) {
            int e = tid + 256*k;
            *(float4*)(smem + (e >> 3)*PITCH + (e & 7)*16) = q4[e];
        }
    }
    __syncthreads();

    uint32_t qf[4][4];
    {
        int r  = 16*wid + (lane & 15);
        int cg = (lane >> 4) & 1;
        #pragma unroll
        for (int kt = 0; kt < 4; kt++)
            LDSM4(qf[kt], sb + r*PITCH + (kt*16 + cg*8)*2);
    }
    __syncthreads();   // Q reads done before cp.async overwrites buf0

    // ---- prologue: async-load tiles 0 and 1; wmT while they fly ----
    load_tile_async(sb, 0, kg, vg, 0,  tid); CP_COMMIT();
    load_tile_async(sb, 1, kg, vg, 64, tid); CP_COMMIT();
    #pragma unroll
    for (int k = 0; k < 16; k++) {
        int e = tid + 256*k;
        wmT[(e & 63)*64 + (e >> 6)] = wm[e];
    }
    CP_WAIT1();        // tile 0 complete
    __syncthreads();

    float oacc[8][4];
    #pragma unroll
    for (int j = 0; j < 8; j++)
        #pragma unroll
        for (int c = 0; c < 4; c++) oacc[j][c] = 0.f;
    float l0 = 0.f, l1 = 0.f;

    const uint32_t klane = ((lane & 7) + ((lane >> 4) & 1)*8)*PITCH + ((lane >> 3) & 1)*16;
    const uint32_t vlane = 9216 + ((lane & 7) + ((lane >> 3) & 1)*8)*PITCH + ((lane >> 4) & 1)*16;

    int cur = 0;
    for (int t = 0; t < 64; t++) {
        // issue tile t+2 into buffer (cur+2)%3 (consumed at iter t-1; barrier passed)
        if (t < 62) {
            int nb = (cur == 0) ? 2 : cur - 1;
            load_tile_async(sb, nb, kg, vg, (t + 2) << 6, tid);
            CP_COMMIT();
        }

        const uint32_t base = sb + cur*KVBUF;

        // ---- S = Q K^T ----
        float sacc[8][4];
        #pragma unroll
        for (int j = 0; j < 8; j++)
            #pragma unroll
            for (int c = 0; c < 4; c++) sacc[j][c] = 0.f;

        const uint32_t kb = base + klane;
        #pragma unroll
        for (int ks = 0; ks < 4; ks++) {
            uint32_t kf0[4], kf1[4], kf2[4], kf3[4];
            LDSM4(kf0, kb + 0*(16*PITCH) + ks*32);
            LDSM4(kf1, kb + 1*(16*PITCH) + ks*32);
            LDSM4(kf2, kb + 2*(16*PITCH) + ks*32);
            LDSM4(kf3, kb + 3*(16*PITCH) + ks*32);
            MMA16816(sacc[0], qf[ks], kf0[0], kf0[1]);
            MMA16816(sacc[1], qf[ks], kf0[2], kf0[3]);
            MMA16816(sacc[2], qf[ks], kf1[0], kf1[1]);
            MMA16816(sacc[3], qf[ks], kf1[2], kf1[3]);
            MMA16816(sacc[4], qf[ks], kf2[0], kf2[1]);
            MMA16816(sacc[5], qf[ks], kf2[2], kf2[3]);
            MMA16816(sacc[6], qf[ks], kf3[0], kf3[1]);
            MMA16816(sacc[7], qf[ks], kf3[2], kf3[3]);
        }

        // ---- per 16-key chunk: f32 exp2 + row sums + pack + O-MMAs ----
        const uint32_t vb = base + vlane;
        #pragma unroll
        for (int ks = 0; ks < 4; ks++) {
            float* s0 = sacc[2*ks];
            float* s1 = sacc[2*ks + 1];
            s0[0] = fexp2(s0[0]); s0[1] = fexp2(s0[1]);
            s0[2] = fexp2(s0[2]); s0[3] = fexp2(s0[3]);
            s1[0] = fexp2(s1[0]); s1[1] = fexp2(s1[1]);
            s1[2] = fexp2(s1[2]); s1[3] = fexp2(s1[3]);
            l0 += s0[0] + s0[1] + s1[0] + s1[1];
            l1 += s0[2] + s0[3] + s1[2] + s1[3];

            uint32_t ph[4];
            __half2 h0 = __floats2half2_rn(s0[0], s0[1]);
            __half2 h1 = __floats2half2_rn(s0[2], s0[3]);
            __half2 h2 = __floats2half2_rn(s1[0], s1[1]);
            __half2 h3 = __floats2half2_rn(s1[2], s1[3]);
            ph[0] = *reinterpret_cast<uint32_t*>(&h0);
            ph[1] = *reinterpret_cast<uint32_t*>(&h1);
            ph[2] = *reinterpret_cast<uint32_t*>(&h2);
            ph[3] = *reinterpret_cast<uint32_t*>(&h3);

            #pragma unroll
            for (int cg = 0; cg < 4; cg++) {
                uint32_t vf[4];
                LDSM4T(vf, vb + ks*(16*PITCH) + cg*32);
                MMA16816(oacc[2*cg],   ph, vf[0], vf[1]);
                MMA16816(oacc[2*cg+1], ph, vf[2], vf[3]);
            }
        }

        // tile t+1 complete for this thread, then make visible to all
        if (t < 62) CP_WAIT1(); else CP_WAIT0();
        __syncthreads();
        cur = (cur == 2) ? 0 : cur + 1;
    }

    // ---- epilogue: normalize, mix GEMM + ReLU, 2x2 pool, store ----
    l0 += __shfl_xor_sync(0xffffffffu, l0, 1);
    l0 += __shfl_xor_sync(0xffffffffu, l0, 2);
    l1 += __shfl_xor_sync(0xffffffffu, l1, 1);
    l1 += __shfl_xor_sync(0xffffffffu, l1, 2);
    float inv0 = 1.f / l0, inv1 = 1.f / l1;

    float* sm_o = (float*)smem;     // o^T [64 c][132]
    {
        int r  = 16*wid + (lane >> 2);
        int c0 = 2*(lane & 3);
        #pragma unroll
        for (int j = 0; j < 8; j++) {
            sm_o[(8*j + c0    )*132 + r]     = oacc[j][0]*inv0;
            sm_o[(8*j + c0 + 1)*132 + r]     = oacc[j][1]*inv0;
            sm_o[(8*j + c0    )*132 + r + 8] = oacc[j][2]*inv1;
            sm_o[(8*j + c0 + 1)*132 + r + 8] = oacc[j][3]*inv1;
        }
    }
    __syncthreads();

    // mix GEMM: mixed[t][d] = relu(bm[d] + sum_c o[t][c]*wm[d][c])
    int tx = tid & 15, ty = tid >> 4;
    float4 bmv = ((const float4*)bm)[tx];
    float acc[8][4];
    #pragma unroll
    for (int ii = 0; ii < 8; ii++) {
        acc[ii][0] = bmv.x; acc[ii][1] = bmv.y; acc[ii][2] = bmv.z; acc[ii][3] = bmv.w;
    }
    #pragma unroll 8
    for (int c = 0; c < 64; c++) {
        float4 wv = *(const float4*)(wmT + c*64 + 4*tx);
        float4 o0 = *(const float4*)(sm_o + c*132 + 8*ty);
        float4 o1 = *(const float4*)(sm_o + c*132 + 8*ty + 4);
        float ov[8] = {o0.x,o0.y,o0.z,o0.w,o1.x,o1.y,o1.z,o1.w};
        #pragma unroll
        for (int ii = 0; ii < 8; ii++) {
            acc[ii][0] = fmaf(ov[ii], wv.x, acc[ii][0]);
            acc[ii][1] = fmaf(ov[ii], wv.y, acc[ii][1]);
            acc[ii][2] = fmaf(ov[ii], wv.z, acc[ii][2]);
            acc[ii][3] = fmaf(ov[ii], wv.w, acc[ii][3]);
        }
    }
    __syncthreads();   // done reading sm_o

    float* sm_mx = (float*)smem;    // mixed [128 t][68]
    #pragma unroll
    for (int ii = 0; ii < 8; ii++) {
        float4 mv = make_float4(fmaxf(acc[ii][0], 0.f), fmaxf(acc[ii][1], 0.f),
                                fmaxf(acc[ii][2], 0.f), fmaxf(acc[ii][3], 0.f));
        *(float4*)(sm_mx + (8*ty + ii)*68 + 4*tx) = mv;
    }
    __syncthreads();

    float* ob = out + (size_t)b*C_*1024 + (size_t)it*32;
    #pragma unroll
    for (int k = 0; k < 8; k++) {
        int e = tid + 256*k;
        int j = e & 31, d = e >> 5;
        float v = sm_mx[(2*j)*68 + d] + sm_mx[(2*j + 1)*68 + d]
                + sm_mx[(64 + 2*j)*68 + d] + sm_mx[(64 + 2*j + 1)*68 + d];
        ob[(size_t)d*1024 + j] = 0.25f * v;
    }
}

extern "C" void kernel_launch(void* const* d_in, const int* in_sizes, int n_in,
                              void* d_out, int out_size)
{
    const float* x  = (const float*)d_in[0];
    const float* wq = (const float*)d_in[1];
    const float* bq = (const float*)d_in[2];
    const float* wk = (const float*)d_in[3];
    const float* bk = (const float*)d_in[4];
    const float* wv = (const float*)d_in[5];
    const float* bv = (const float*)d_in[6];
    const float* wm = (const float*)d_in[7];
    const float* bm = (const float*)d_in[8];
    float* out = (float*)d_out;

    cudaFuncSetAttribute(qkv_kernel,  cudaFuncAttributeMaxDynamicSharedMemorySize, QKV_SMEM);
    cudaFuncSetAttribute(attn_kernel, cudaFuncAttributeMaxDynamicSharedMemorySize, ATTN_SMEM);

    qkv_kernel<<<512, 256, QKV_SMEM>>>(x, wq, bq, wk, bk, wv, bv);
    attn_kernel<<<256, 256, ATTN_SMEM>>>(wm, bm, out);
}

// round 10
// speedup vs baseline: 1.5931x; 1.0113x over previous
#include <cuda_runtime.h>
#include <cuda_fp16.h>
#include <cstdint>

#define B_  8
#define C_  64
#define HW_ 4096

// ---------------- scratch globals (no allocation) ----------------
__device__ __half g_q[(size_t)B_*HW_*C_];   // [b][n][c]  (scaled by log2e/8)
__device__ __half g_k[(size_t)B_*HW_*C_];   // [b][n][c]
__device__ __half g_v[(size_t)B_*HW_*C_];   // [b][n][c]

__device__ __forceinline__ uint32_t smem_u32(const void* p) {
    uint32_t a;
    asm("{ .reg .u64 t; cvta.to.shared.u64 t, %1; cvt.u32.u64 %0, t; }" : "=r"(a) : "l"(p));
    return a;
}

#define MMA16816(c, a, b0, b1)                                                  \
    asm volatile("mma.sync.aligned.m16n8k16.row.col.f32.f16.f16.f32 "           \
        "{%0,%1,%2,%3}, {%4,%5,%6,%7}, {%8,%9}, {%0,%1,%2,%3};"                 \
        : "+f"((c)[0]), "+f"((c)[1]), "+f"((c)[2]), "+f"((c)[3])                \
        : "r"((a)[0]), "r"((a)[1]), "r"((a)[2]), "r"((a)[3]), "r"(b0), "r"(b1))

#define LDSM4(r, a)                                                             \
    asm volatile("ldmatrix.sync.aligned.m8n8.x4.shared.b16 {%0,%1,%2,%3}, [%4];"\
        : "=r"((r)[0]), "=r"((r)[1]), "=r"((r)[2]), "=r"((r)[3]) : "r"(a))

#define LDSM4T(r, a)                                                            \
    asm volatile("ldmatrix.sync.aligned.m8n8.x4.trans.shared.b16 {%0,%1,%2,%3}, [%4];"\
        : "=r"((r)[0]), "=r"((r)[1]), "=r"((r)[2]), "=r"((r)[3]) : "r"(a))

#define CP16(dst, src) asm volatile("cp.async.cg.shared.global [%0], [%1], 16;" :: "r"(dst), "l"(src))
#define CP_COMMIT()    asm volatile("cp.async.commit_group;" ::: "memory")
#define CP_WAIT1()     asm volatile("cp.async.wait_group 1;" ::: "memory")
#define CP_WAIT0()     asm volatile("cp.async.wait_group 0;" ::: "memory")

// hardware exp2 (MUFU.EX2 f32, rel err ~1e-6)
__device__ __forceinline__ float fexp2(float x) {
    float y;
    asm("ex2.approx.f32 %0, %1;" : "=f"(y) : "f"(x));
    return y;
}

// ---------------------------------------------------------------------------
// QKV projection, all three matrices in one pass over the x tile.
// ---------------------------------------------------------------------------
#define QKV_SMEM (64*68*4 + 3*64*65*4 + 3*64*4)

__global__ __launch_bounds__(256) void qkv_kernel(
    const float* __restrict__ x,
    const float* __restrict__ wq, const float* __restrict__ bq,
    const float* __restrict__ wk, const float* __restrict__ bk,
    const float* __restrict__ wv, const float* __restrict__ bv)
{
    extern __shared__ float smf[];
    float* xs  = smf;                 // [64][68]
    float* ws  = smf + 64*68;         // 3 x [64][65]
    float* bsh = ws + 3*64*65;        // 3 x 64

    int tid = threadIdx.x;
    int b   = blockIdx.x >> 6;
    int n0  = (blockIdx.x & 63) << 6;
    const float* xb = x + (size_t)b*C_*HW_;

    #pragma unroll
    for (int k = 0; k < 16; k++) {
        int e = tid + 256*k; int c = e >> 6, i = e & 63;
        xs[c*68 + i] = xb[(size_t)c*HW_ + n0 + i];
    }
    #pragma unroll
    for (int k = 0; k < 16; k++) {
        int e = tid + 256*k;
        int c = e & 63, d = e >> 6;
        ws[c*65 + d]          = wq[e];
        ws[4160 + c*65 + d]   = wk[e];
        ws[8320 + c*65 + d]   = wv[e];
    }
    if (tid < 192) {
        bsh[tid] = (tid < 64) ? bq[tid] : (tid < 128) ? bk[tid - 64] : bv[tid - 128];
    }
    __syncthreads();

    int d = tid & 63, ib = (tid >> 6) << 4;
    float acc[3][16];
    #pragma unroll
    for (int k = 0; k < 16; k++) {
        acc[0][k] = bsh[d]; acc[1][k] = bsh[64 + d]; acc[2][k] = bsh[128 + d];
    }

    #pragma unroll 8
    for (int c = 0; c < 64; c++) {
        const float4* xr = (const float4*)(xs + c*68 + ib);
        float4 x0 = xr[0], x1 = xr[1], x2 = xr[2], x3 = xr[3];
        float xv[16] = {x0.x,x0.y,x0.z,x0.w, x1.x,x1.y,x1.z,x1.w,
                        x2.x,x2.y,x2.z,x2.w, x3.x,x3.y,x3.z,x3.w};
        float w0 = ws[c*65 + d], w1 = ws[4160 + c*65 + d], w2 = ws[8320 + c*65 + d];
        #pragma unroll
        for (int k = 0; k < 16; k++) {
            acc[0][k] = fmaf(xv[k], w0, acc[0][k]);
            acc[1][k] = fmaf(xv[k], w1, acc[1][k]);
            acc[2][k] = fmaf(xv[k], w2, acc[2][k]);
        }
    }

    const float scq = 0.18033688011112043f;   // log2(e)/8
    __half* qo = g_q + (size_t)b*HW_*C_;
    __half* ko = g_k + (size_t)b*HW_*C_;
    __half* vo = g_v + (size_t)b*HW_*C_;
    #pragma unroll
    for (int k = 0; k < 16; k++) {
        size_t o = (size_t)(n0 + ib + k)*C_ + d;
        qo[o] = __float2half_rn(acc[0][k]*scq);
        ko[o] = __float2half_rn(acc[1][k]);
        vo[o] = __float2half_rn(acc[2][k]);
    }
}

// ---------------------------------------------------------------------------
// Fused flash attention with warp-parity pipeline:
//   warps 0-3: S(t) -> softmax(t) -> O(t)
//   warps 4-7: O(t-1) -> S(t) -> softmax(t)   (carry packed P, 16 regs)
// so MUFU-heavy softmax of one group overlaps tensor-heavy MMA of the other.
// K ring 3 stages, V ring 4 stages (V(t-1) must survive for the carry group).
// Epilogue: normalize + mix GEMM + ReLU + 2x2 avg pool.
// ---------------------------------------------------------------------------
#define PITCH 144                  // bytes per 64-half row (8 halves padding)
#define TILEB 9216                 // one 64-key K or V tile (64 rows * 144B)
#define SM_K  0                    // K stages: 0, 9216, 18432
#define SM_V  27648                // V stages: 27648 + i*9216, i=0..3
#define SM_WMT 64512               // wmT (16 KB)
#define ATTN_SMEM (64512 + 16384)

__device__ __forceinline__ void load_tile_async(
    uint32_t sb, int kst, int vst, const __half* kg, const __half* vg, int kn0, int tid)
{
    uint32_t kd = sb + SM_K + kst*TILEB;
    uint32_t vd = sb + SM_V + vst*TILEB;
    const char* ksrc = (const char*)(kg + (size_t)kn0*C_);
    const char* vsrc = (const char*)(vg + (size_t)kn0*C_);
    #pragma unroll
    for (int k = 0; k < 2; k++) {
        int e = tid + 256*k;
        uint32_t doff = (e >> 3)*PITCH + (e & 7)*16;
        CP16(kd + doff, ksrc + e*16);
        CP16(vd + doff, vsrc + e*16);
    }
}

__device__ __forceinline__ void s_mma(uint32_t kb, const uint32_t (&qf)[4][4], float (&sacc)[8][4])
{
    #pragma unroll
    for (int j = 0; j < 8; j++)
        #pragma unroll
        for (int c = 0; c < 4; c++) sacc[j][c] = 0.f;
    #pragma unroll
    for (int ks = 0; ks < 4; ks++) {
        uint32_t kf0[4], kf1[4], kf2[4], kf3[4];
        LDSM4(kf0, kb + 0*(16*PITCH) + ks*32);
        LDSM4(kf1, kb + 1*(16*PITCH) + ks*32);
        LDSM4(kf2, kb + 2*(16*PITCH) + ks*32);
        LDSM4(kf3, kb + 3*(16*PITCH) + ks*32);
        MMA16816(sacc[0], qf[ks], kf0[0], kf0[1]);
        MMA16816(sacc[1], qf[ks], kf0[2], kf0[3]);
        MMA16816(sacc[2], qf[ks], kf1[0], kf1[1]);
        MMA16816(sacc[3], qf[ks], kf1[2], kf1[3]);
        MMA16816(sacc[4], qf[ks], kf2[0], kf2[1]);
        MMA16816(sacc[5], qf[ks], kf2[2], kf2[3]);
        MMA16816(sacc[6], qf[ks], kf3[0], kf3[1]);
        MMA16816(sacc[7], qf[ks], kf3[2], kf3[3]);
    }
}

__device__ __forceinline__ void softmax_pack(
    float (&sacc)[8][4], uint32_t (&ph)[4][4], float& l0, float& l1)
{
    #pragma unroll
    for (int ks = 0; ks < 4; ks++) {
        float* s0 = sacc[2*ks];
        float* s1 = sacc[2*ks + 1];
        s0[0] = fexp2(s0[0]); s0[1] = fexp2(s0[1]);
        s0[2] = fexp2(s0[2]); s0[3] = fexp2(s0[3]);
        s1[0] = fexp2(s1[0]); s1[1] = fexp2(s1[1]);
        s1[2] = fexp2(s1[2]); s1[3] = fexp2(s1[3]);
        l0 += s0[0] + s0[1] + s1[0] + s1[1];
        l1 += s0[2] + s0[3] + s1[2] + s1[3];
        __half2 h0 = __floats2half2_rn(s0[0], s0[1]);
        __half2 h1 = __floats2half2_rn(s0[2], s0[3]);
        __half2 h2 = __floats2half2_rn(s1[0], s1[1]);
        __half2 h3 = __floats2half2_rn(s1[2], s1[3]);
        ph[ks][0] = *reinterpret_cast<uint32_t*>(&h0);
        ph[ks][1] = *reinterpret_cast<uint32_t*>(&h1);
        ph[ks][2] = *reinterpret_cast<uint32_t*>(&h2);
        ph[ks][3] = *reinterpret_cast<uint32_t*>(&h3);
    }
}

__device__ __forceinline__ void o_mma(
    uint32_t vb, const uint32_t (&ph)[4][4], float (&oacc)[8][4])
{
    #pragma unroll
    for (int ks = 0; ks < 4; ks++) {
        #pragma unroll
        for (int cg = 0; cg < 4; cg++) {
            uint32_t vf[4];
            LDSM4T(vf, vb + ks*(16*PITCH) + cg*32);
            MMA16816(oacc[2*cg],   ph[ks], vf[0], vf[1]);
            MMA16816(oacc[2*cg+1], ph[ks], vf[2], vf[3]);
        }
    }
}

__global__ __launch_bounds__(256, 2) void attn_kernel(
    const float* __restrict__ wm, const float* __restrict__ bm,
    float* __restrict__ out)
{
    extern __shared__ __align__(16) char smem[];
    const uint32_t sb = smem_u32(smem);
    float* wmT = (float*)(smem + SM_WMT);   // wmT[c][d]

    int tid = threadIdx.x, wid = tid >> 5, lane = tid & 31;
    int b  = blockIdx.x >> 5;
    int it = blockIdx.x & 31;          // output row index
    int n0 = it << 7;

    const __half* kg = g_k + (size_t)b*HW_*C_;
    const __half* vg = g_v + (size_t)b*HW_*C_;

    // ---- stage Q (overlays K stages 0-1), load A fragments ----
    {
        const float4* q4 = (const float4*)(g_q + ((size_t)b*HW_ + n0)*C_);
        #pragma unroll
        for (int k = 0; k < 4; k++) {
            int e = tid + 256*k;
            *(float4*)(smem + (e >> 3)*PITCH + (e & 7)*16) = q4[e];
        }
    }
    __syncthreads();

    uint32_t qf[4][4];
    {
        int r  = 16*wid + (lane & 15);
        int cg = (lane >> 4) & 1;
        #pragma unroll
        for (int kt = 0; kt < 4; kt++)
            LDSM4(qf[kt], sb + r*PITCH + (kt*16 + cg*8)*2);
    }
    __syncthreads();   // Q reads done before cp.async overwrites K stage 0

    // ---- prologue: async tile 0; wmT while it flies ----
    load_tile_async(sb, 0, 0, kg, vg, 0, tid); CP_COMMIT();
    #pragma unroll
    for (int k = 0; k < 16; k++) {
        int e = tid + 256*k;
        wmT[(e & 63)*64 + (e >> 6)] = wm[e];
    }

    float oacc[8][4];
    #pragma unroll
    for (int j = 0; j < 8; j++)
        #pragma unroll
        for (int c = 0; c < 4; c++) oacc[j][c] = 0.f;
    float l0 = 0.f, l1 = 0.f;
    uint32_t phs[4][4];   // carried packed P (warps 4-7)

    const uint32_t klane = ((lane & 7) + ((lane >> 4) & 1)*8)*PITCH + ((lane >> 3) & 1)*16;
    const uint32_t vlane = ((lane & 7) + ((lane >> 3) & 1)*8)*PITCH + ((lane >> 4) & 1)*16;

    for (int t = 0; t < 64; t++) {
        // issue tile t+1; buffer being overwritten was last read at iter t-2,
        // and the barrier inside iter t-1 ordered that before this write.
        if (t < 63) {
            load_tile_async(sb, (t+1)%3, (t+1)&3, kg, vg, (t+1) << 6, tid);
            CP_COMMIT();
            CP_WAIT1();    // own copies of tile t complete
        } else {
            CP_WAIT0();
        }
        __syncthreads();   // tile t visible CTA-wide; iter t-1 compute done

        const uint32_t kb   = sb + SM_K + (t%3)*TILEB + klane;
        const uint32_t vcur = sb + SM_V + (t&3)*TILEB + vlane;
        float sacc[8][4];

        if (wid < 4) {
            uint32_t ph[4][4];
            s_mma(kb, qf, sacc);
            softmax_pack(sacc, ph, l0, l1);
            o_mma(vcur, ph, oacc);
        } else {
            if (t > 0) {
                const uint32_t vprev = sb + SM_V + ((t+3)&3)*TILEB + vlane;
                o_mma(vprev, phs, oacc);
            }
            s_mma(kb, qf, sacc);
            softmax_pack(sacc, phs, l0, l1);
        }
    }
    if (wid >= 4) {
        const uint32_t vlast = sb + SM_V + (63&3)*TILEB + vlane;
        o_mma(vlast, phs, oacc);
    }

    // ---- epilogue: normalize, mix GEMM + ReLU, 2x2 pool, store ----
    l0 += __shfl_xor_sync(0xffffffffu, l0, 1);
    l0 += __shfl_xor_sync(0xffffffffu, l0, 2);
    l1 += __shfl_xor_sync(0xffffffffu, l1, 1);
    l1 += __shfl_xor_sync(0xffffffffu, l1, 2);
    float inv0 = 1.f / l0, inv1 = 1.f / l1;

    __syncthreads();   // all K/V reads done; reuse smem (below wmT)
    float* sm_o = (float*)smem;     // o^T [64 c][132] = 33792 B
    {
        int r  = 16*wid + (lane >> 2);
        int c0 = 2*(lane & 3);
        #pragma unroll
        for (int j = 0; j < 8; j++) {
            sm_o[(8*j + c0    )*132 + r]     = oacc[j][0]*inv0;
            sm_o[(8*j + c0 + 1)*132 + r]     = oacc[j][1]*inv0;
            sm_o[(8*j + c0    )*132 + r + 8] = oacc[j][2]*inv1;
            sm_o[(8*j + c0 + 1)*132 + r + 8] = oacc[j][3]*inv1;
        }
    }
    __syncthreads();

    // mix GEMM: mixed[t][d] = relu(bm[d] + sum_c o[t][c]*wm[d][c])
    int tx = tid & 15, ty = tid >> 4;
    float4 bmv = ((const float4*)bm)[tx];
    float acc[8][4];
    #pragma unroll
    for (int ii = 0; ii < 8; ii++) {
        acc[ii][0] = bmv.x; acc[ii][1] = bmv.y; acc[ii][2] = bmv.z; acc[ii][3] = bmv.w;
    }
    #pragma unroll 8
    for (int c = 0; c < 64; c++) {
        float4 wv = *(const float4*)(wmT + c*64 + 4*tx);
        float4 o0 = *(const float4*)(sm_o + c*132 + 8*ty);
        float4 o1 = *(const float4*)(sm_o + c*132 + 8*ty + 4);
        float ov[8] = {o0.x,o0.y,o0.z,o0.w,o1.x,o1.y,o1.z,o1.w};
        #pragma unroll
        for (int ii = 0; ii < 8; ii++) {
            acc[ii][0] = fmaf(ov[ii], wv.x, acc[ii][0]);
            acc[ii][1] = fmaf(ov[ii], wv.y, acc[ii][1]);
            acc[ii][2] = fmaf(ov[ii], wv.z, acc[ii][2]);
            acc[ii][3] = fmaf(ov[ii], wv.w, acc[ii][3]);
        }
    }
    __syncthreads();   // done reading sm_o

    float* sm_mx = (float*)smem;    // mixed [128 t][68] = 34816 B
    #pragma unroll
    for (int ii = 0; ii < 8; ii++) {
        float4 mv = make_float4(fmaxf(acc[ii][0], 0.f), fmaxf(acc[ii][1], 0.f),
                                fmaxf(acc[ii][2], 0.f), fmaxf(acc[ii][3], 0.f));
        *(float4*)(sm_mx + (8*ty + ii)*68 + 4*tx) = mv;
    }
    __syncthreads();

    float* ob = out + (size_t)b*C_*1024 + (size_t)it*32;
    #pragma unroll
    for (int k = 0; k < 8; k++) {
        int e = tid + 256*k;
        int j = e & 31, d = e >> 5;
        float v = sm_mx[(2*j)*68 + d] + sm_mx[(2*j + 1)*68 + d]
                + sm_mx[(64 + 2*j)*68 + d] + sm_mx[(64 + 2*j + 1)*68 + d];
        ob[(size_t)d*1024 + j] = 0.25f * v;
    }
}

extern "C" void kernel_launch(void* const* d_in, const int* in_sizes, int n_in,
                              void* d_out, int out_size)
{
    const float* x  = (const float*)d_in[0];
    const float* wq = (const float*)d_in[1];
    const float* bq = (const float*)d_in[2];
    const float* wk = (const float*)d_in[3];
    const float* bk = (const float*)d_in[4];
    const float* wv = (const float*)d_in[5];
    const float* bv = (const float*)d_in[6];
    const float* wm = (const float*)d_in[7];
    const float* bm = (const float*)d_in[8];
    float* out = (float*)d_out;

    cudaFuncSetAttribute(qkv_kernel,  cudaFuncAttributeMaxDynamicSharedMemorySize, QKV_SMEM);
    cudaFuncSetAttribute(attn_kernel, cudaFuncAttributeMaxDynamicSharedMemorySize, ATTN_SMEM);

    qkv_kernel<<<512, 256, QKV_SMEM>>>(x, wq, bq, wk, bk, wv, bv);
    attn_kernel<<<256, 256, ATTN_SMEM>>>(wm, bm, out);
}